// round 1
// baseline (speedup 1.0000x reference)
#include <cuda_runtime.h>
#include <math.h>

// Problem constants
#define B_    128
#define N_    4096
#define D_    384
#define K_    5
#define H1_   1024
#define H2_   512
#define XXDIM ((K_ + 1) * D_)   // 2304

// Scratch (no cudaMalloc allowed)
__device__ float g_xx[B_ * XXDIM];
__device__ float g_h1[B_ * H1_];
__device__ float g_h2[B_ * H1_];
__device__ float g_h3[B_ * H1_];
__device__ float g_h4[B_ * H2_];

// ---------------------------------------------------------------------------
// Kernel 1: per-article sims + top-5 + gather into xx
// grid = 128 (one block per article b), block = 512 threads (16 warps)
// ---------------------------------------------------------------------------
__global__ __launch_bounds__(512) void sims_topk_gather(
    const float* __restrict__ stance,   // [B, D]
    const float* __restrict__ body,     // [B, N, D]
    float* __restrict__ xx)             // [B, (K+1)*D]
{
    __shared__ float s_sims[N_];
    __shared__ int   s_idx[K_];

    const int b    = blockIdx.x;
    const int tid  = threadIdx.x;
    const int lane = tid & 31;
    const int warp = tid >> 5;
    const int NW   = blockDim.x >> 5;   // 16 warps

    // stance row held in registers, split across lanes (96 float4 per row)
    const float4* S = reinterpret_cast<const float4*>(stance + (size_t)b * D_);
    const float4 s0 = S[lane];
    const float4 s1 = S[lane + 32];
    const float4 s2 = S[lane + 64];

    const float4* Bp = reinterpret_cast<const float4*>(body + (size_t)b * N_ * D_);

    // 2 rows per warp iteration for extra MLP
    for (int n = warp * 2; n < N_; n += NW * 2) {
        const float4* r0 = Bp + (size_t)n * 96;
        const float4* r1 = Bp + (size_t)(n + 1) * 96;
        float4 a0 = r0[lane],  a1 = r0[lane + 32], a2 = r0[lane + 64];
        float4 c0 = r1[lane],  c1 = r1[lane + 32], c2 = r1[lane + 64];

        float p = s0.x*a0.x + s0.y*a0.y + s0.z*a0.z + s0.w*a0.w
                + s1.x*a1.x + s1.y*a1.y + s1.z*a1.z + s1.w*a1.w
                + s2.x*a2.x + s2.y*a2.y + s2.z*a2.z + s2.w*a2.w;
        float q = s0.x*c0.x + s0.y*c0.y + s0.z*c0.z + s0.w*c0.w
                + s1.x*c1.x + s1.y*c1.y + s1.z*c1.z + s1.w*c1.w
                + s2.x*c2.x + s2.y*c2.y + s2.z*c2.z + s2.w*c2.w;
        #pragma unroll
        for (int o = 16; o > 0; o >>= 1) {
            p += __shfl_xor_sync(0xffffffffu, p, o);
            q += __shfl_xor_sync(0xffffffffu, q, o);
        }
        if (lane == 0) { s_sims[n] = p; s_sims[n + 1] = q; }
    }
    __syncthreads();

    // warp 0: 5 argmax passes; tie-break = lower index (matches jax.lax.top_k)
    if (warp == 0) {
        for (int r = 0; r < K_; r++) {
            float bv = -INFINITY;
            int   bi = N_;
            for (int n = lane; n < N_; n += 32) {
                float v = s_sims[n];
                if (v > bv) { bv = v; bi = n; }   // strict > keeps lowest index per lane
            }
            #pragma unroll
            for (int o = 16; o > 0; o >>= 1) {
                float ov = __shfl_xor_sync(0xffffffffu, bv, o);
                int   oi = __shfl_xor_sync(0xffffffffu, bi, o);
                if (ov > bv || (ov == bv && oi < bi)) { bv = ov; bi = oi; }
            }
            if (lane == 0) { s_idx[r] = bi; s_sims[bi] = -INFINITY; }
            __syncwarp();
        }
    }
    __syncthreads();

    // gather: xx[b] = concat(stance[b], body[b, idx0], ..., body[b, idx4])
    float* xrow = xx + (size_t)b * XXDIM;
    for (int c = tid; c < D_; c += blockDim.x)
        xrow[c] = stance[(size_t)b * D_ + c];
    for (int e = tid; e < K_ * D_; e += blockDim.x) {
        int r = e / D_, c = e - r * D_;
        xrow[D_ + e] = body[((size_t)b * N_ + s_idx[r]) * D_ + c];
    }
}

// ---------------------------------------------------------------------------
// Generic tiled SGEMM: Y[M,N] = act(X[M,K] @ W[N,K]^T + bias)
// BM=BN=BK=32, 256 threads, 2x2 microtile. All dims divisible by 32.
// ---------------------------------------------------------------------------
template <int RELU>
__global__ __launch_bounds__(256) void gemm_bias_act(
    const float* __restrict__ X, const float* __restrict__ W,
    const float* __restrict__ bias, float* __restrict__ Y,
    int M, int N, int Kin)
{
    __shared__ float Xs[32][33];
    __shared__ float Ws[32][33];

    const int t  = threadIdx.x;          // 0..255
    const int tx = t & 15;               // n direction
    const int ty = t >> 4;               // m direction
    const int m0 = blockIdx.y * 32;
    const int n0 = blockIdx.x * 32;

    float acc00 = 0.f, acc01 = 0.f, acc10 = 0.f, acc11 = 0.f;

    for (int k0 = 0; k0 < Kin; k0 += 32) {
        #pragma unroll
        for (int j = 0; j < 4; j++) {
            int e  = t + j * 256;
            int mi = e >> 5;
            int ki = e & 31;
            Xs[ki][mi] = X[(size_t)(m0 + mi) * Kin + k0 + ki];
            Ws[ki][mi] = W[(size_t)(n0 + mi) * Kin + k0 + ki];
        }
        __syncthreads();
        #pragma unroll
        for (int k = 0; k < 32; k++) {
            float a0 = Xs[k][ty * 2], a1 = Xs[k][ty * 2 + 1];
            float w0 = Ws[k][tx * 2], w1 = Ws[k][tx * 2 + 1];
            acc00 = fmaf(a0, w0, acc00);
            acc01 = fmaf(a0, w1, acc01);
            acc10 = fmaf(a1, w0, acc10);
            acc11 = fmaf(a1, w1, acc11);
        }
        __syncthreads();
    }

    const int m = m0 + ty * 2;
    const int n = n0 + tx * 2;
    float v00 = acc00 + bias[n],     v01 = acc01 + bias[n + 1];
    float v10 = acc10 + bias[n],     v11 = acc11 + bias[n + 1];
    if (RELU) {
        v00 = fmaxf(v00, 0.f); v01 = fmaxf(v01, 0.f);
        v10 = fmaxf(v10, 0.f); v11 = fmaxf(v11, 0.f);
    }
    Y[(size_t)m * N + n]           = v00;
    Y[(size_t)m * N + n + 1]       = v01;
    Y[(size_t)(m + 1) * N + n]     = v10;
    Y[(size_t)(m + 1) * N + n + 1] = v11;
}

// ---------------------------------------------------------------------------
// Final layer: [128, 512] @ [2, 512]^T + b5 -> [128, 2]
// ---------------------------------------------------------------------------
__global__ __launch_bounds__(256) void final_layer(
    const float* __restrict__ X, const float* __restrict__ W,
    const float* __restrict__ bias, float* __restrict__ out)
{
    const int t = threadIdx.x;           // 256 = 128 rows * 2 cols
    const int m = t >> 1;
    const int c = t & 1;
    const float* xr = X + (size_t)m * H2_;
    const float* wr = W + (size_t)c * H2_;
    float acc = 0.f;
    #pragma unroll 8
    for (int k = 0; k < H2_; k++) acc = fmaf(xr[k], wr[k], acc);
    out[m * 2 + c] = acc + bias[c];
}

// ---------------------------------------------------------------------------
// Launch
// ---------------------------------------------------------------------------
extern "C" void kernel_launch(void* const* d_in, const int* in_sizes, int n_in,
                              void* d_out, int out_size)
{
    const float* stance = (const float*)d_in[0];   // sim_stance_emb [128,384]
    // d_in[1] nli_stance_emb (unused)
    const float* body   = (const float*)d_in[2];   // sim_body_emb [128,4096,384]
    // d_in[3] nli_body_emb (unused)
    const float* W1 = (const float*)d_in[4];  const float* b1 = (const float*)d_in[5];
    const float* W2 = (const float*)d_in[6];  const float* b2 = (const float*)d_in[7];
    const float* W3 = (const float*)d_in[8];  const float* b3 = (const float*)d_in[9];
    const float* W4 = (const float*)d_in[10]; const float* b4 = (const float*)d_in[11];
    const float* W5 = (const float*)d_in[12]; const float* b5 = (const float*)d_in[13];

    float *xx, *h1, *h2, *h3, *h4;
    cudaGetSymbolAddress((void**)&xx, g_xx);
    cudaGetSymbolAddress((void**)&h1, g_h1);
    cudaGetSymbolAddress((void**)&h2, g_h2);
    cudaGetSymbolAddress((void**)&h3, g_h3);
    cudaGetSymbolAddress((void**)&h4, g_h4);

    sims_topk_gather<<<B_, 512>>>(stance, body, xx);

    gemm_bias_act<1><<<dim3(H1_ / 32, B_ / 32), 256>>>(xx, W1, b1, h1, B_, H1_, XXDIM);
    gemm_bias_act<1><<<dim3(H1_ / 32, B_ / 32), 256>>>(h1, W2, b2, h2, B_, H1_, H1_);
    gemm_bias_act<1><<<dim3(H1_ / 32, B_ / 32), 256>>>(h2, W3, b3, h3, B_, H1_, H1_);
    gemm_bias_act<1><<<dim3(H2_ / 32, B_ / 32), 256>>>(h3, W4, b4, h4, B_, H2_, H1_);

    final_layer<<<1, 256>>>(h4, W5, b5, (float*)d_out);
}

// round 2
// speedup vs baseline: 1.8418x; 1.8418x over previous
#include <cuda_runtime.h>
#include <math.h>

#define B_    128
#define N_    4096
#define D_    384
#define K_    5
#define H1_   1024
#define H2_   512
#define XXDIM ((K_ + 1) * D_)   // 2304

// Scratch (no cudaMalloc allowed)
__device__ float g_sims[B_ * N_];                 // 2 MB
__device__ float g_xx[B_ * XXDIM];
__device__ float g_h1[B_ * H1_];
__device__ float g_h2[B_ * H1_];
__device__ float g_h3[B_ * H1_];
__device__ float g_h4[B_ * H2_];
__device__ float g_part[9 * B_ * H1_];            // split-K partials (max 9x128x1024)

// ---------------------------------------------------------------------------
// Kernel 1a: sims[b, n] = <stance_b, body_{b,n}>
// grid = (8 chunks, 128 articles), block = 256 (8 warps, 2 rows/warp/iter)
// ---------------------------------------------------------------------------
__global__ __launch_bounds__(256) void sims_dots(
    const float* __restrict__ stance,
    const float* __restrict__ body,
    float* __restrict__ sims)
{
    const int b     = blockIdx.y;
    const int chunk = blockIdx.x;          // 0..7, 512 rows each
    const int lane  = threadIdx.x & 31;
    const int warp  = threadIdx.x >> 5;    // 0..7

    const float4* S = reinterpret_cast<const float4*>(stance + (size_t)b * D_);
    const float4 s0 = S[lane];
    const float4 s1 = S[lane + 32];
    const float4 s2 = S[lane + 64];

    const float4* Bp = reinterpret_cast<const float4*>(
        body + ((size_t)b * N_ + chunk * 512) * D_);
    float* out = sims + (size_t)b * N_ + chunk * 512;

    for (int n = warp * 2; n < 512; n += 16) {
        const float4* r0 = Bp + (size_t)n * 96;
        const float4* r1 = Bp + (size_t)(n + 1) * 96;
        float4 a0 = r0[lane], a1 = r0[lane + 32], a2 = r0[lane + 64];
        float4 c0 = r1[lane], c1 = r1[lane + 32], c2 = r1[lane + 64];

        float p = s0.x*a0.x + s0.y*a0.y + s0.z*a0.z + s0.w*a0.w
                + s1.x*a1.x + s1.y*a1.y + s1.z*a1.z + s1.w*a1.w
                + s2.x*a2.x + s2.y*a2.y + s2.z*a2.z + s2.w*a2.w;
        float q = s0.x*c0.x + s0.y*c0.y + s0.z*c0.z + s0.w*c0.w
                + s1.x*c1.x + s1.y*c1.y + s1.z*c1.z + s1.w*c1.w
                + s2.x*c2.x + s2.y*c2.y + s2.z*c2.z + s2.w*c2.w;
        #pragma unroll
        for (int o = 16; o > 0; o >>= 1) {
            p += __shfl_xor_sync(0xffffffffu, p, o);
            q += __shfl_xor_sync(0xffffffffu, q, o);
        }
        if (lane == 0) { out[n] = p; out[n + 1] = q; }
    }
}

// ---------------------------------------------------------------------------
// Kernel 1b: top-5 per article + gather xx = [stance | top5 bodies]
// grid = 128, block = 256
// ---------------------------------------------------------------------------
__global__ __launch_bounds__(256) void topk_gather(
    const float* __restrict__ stance,
    const float* __restrict__ body,
    const float* __restrict__ sims,
    float* __restrict__ xx)
{
    __shared__ float s_sims[N_];
    __shared__ int   s_idx[K_];

    const int b    = blockIdx.x;
    const int tid  = threadIdx.x;
    const int lane = tid & 31;
    const int warp = tid >> 5;

    // load sims row (16 KB) into smem
    const float4* Sr = reinterpret_cast<const float4*>(sims + (size_t)b * N_);
    float4* Ss = reinterpret_cast<float4*>(s_sims);
    #pragma unroll
    for (int j = 0; j < 4; j++) Ss[tid + j * 256] = Sr[tid + j * 256];
    __syncthreads();

    if (warp == 0) {
        for (int r = 0; r < K_; r++) {
            float bv = -INFINITY;
            int   bi = N_;
            for (int n = lane; n < N_; n += 32) {
                float v = s_sims[n];
                if (v > bv) { bv = v; bi = n; }
            }
            #pragma unroll
            for (int o = 16; o > 0; o >>= 1) {
                float ov = __shfl_xor_sync(0xffffffffu, bv, o);
                int   oi = __shfl_xor_sync(0xffffffffu, bi, o);
                if (ov > bv || (ov == bv && oi < bi)) { bv = ov; bi = oi; }
            }
            if (lane == 0) { s_idx[r] = bi; s_sims[bi] = -INFINITY; }
            __syncwarp();
        }
    }
    __syncthreads();

    float* xrow = xx + (size_t)b * XXDIM;
    for (int c = tid; c < D_; c += 256)
        xrow[c] = stance[(size_t)b * D_ + c];
    for (int e = tid; e < K_ * D_; e += 256) {
        int r = e / D_, c = e - r * D_;
        xrow[D_ + e] = body[((size_t)b * N_ + s_idx[r]) * D_ + c];
    }
}

// ---------------------------------------------------------------------------
// Split-K SGEMM: part[s][128][N-tile] += X[128, kchunk] @ W[64, kchunk]^T
// grid = (N/64, SPLITK), block = 256, tile M=128 x N=64, microtile 8x4
// ---------------------------------------------------------------------------
__global__ __launch_bounds__(256) void gemm_splitk(
    const float* __restrict__ X, const float* __restrict__ W,
    float* __restrict__ part, int N, int Kin, int kchunk)
{
    __shared__ float Xs[32][132];   // [ki][m], padded: stride 132 keeps 16B align
    __shared__ float Ws[32][68];    // [ki][n]

    const int t  = threadIdx.x;
    const int n0 = blockIdx.x * 64;
    const int ks = blockIdx.y * kchunk;
    const int tx = t & 15;          // n group: n = n0 + tx*4
    const int ty = t >> 4;          // m group: m = ty*8

    float acc[8][4];
    #pragma unroll
    for (int i = 0; i < 8; i++)
        #pragma unroll
        for (int j = 0; j < 4; j++) acc[i][j] = 0.f;

    for (int k0 = ks; k0 < ks + kchunk; k0 += 32) {
        // Load Xs: 128 rows x 32 k (1024 float4), 4 per thread, transposed store
        #pragma unroll
        for (int j = 0; j < 4; j++) {
            int id = t + j * 256;
            int m  = id >> 3;            // 0..127
            int kv = id & 7;             // 0..7 (float4 along k)
            float4 v = *reinterpret_cast<const float4*>(
                &X[(size_t)m * Kin + k0 + kv * 4]);
            Xs[kv * 4 + 0][m] = v.x;
            Xs[kv * 4 + 1][m] = v.y;
            Xs[kv * 4 + 2][m] = v.z;
            Xs[kv * 4 + 3][m] = v.w;
        }
        // Load Ws: 64 rows x 32 k (512 float4), 2 per thread
        #pragma unroll
        for (int j = 0; j < 2; j++) {
            int id = t + j * 256;
            int n  = id >> 3;            // 0..63
            int kv = id & 7;
            float4 v = *reinterpret_cast<const float4*>(
                &W[(size_t)(n0 + n) * Kin + k0 + kv * 4]);
            Ws[kv * 4 + 0][n] = v.x;
            Ws[kv * 4 + 1][n] = v.y;
            Ws[kv * 4 + 2][n] = v.z;
            Ws[kv * 4 + 3][n] = v.w;
        }
        __syncthreads();

        #pragma unroll
        for (int k = 0; k < 32; k++) {
            float4 a0 = *reinterpret_cast<const float4*>(&Xs[k][ty * 8]);
            float4 a1 = *reinterpret_cast<const float4*>(&Xs[k][ty * 8 + 4]);
            float4 b0 = *reinterpret_cast<const float4*>(&Ws[k][tx * 4]);
            float a[8] = {a0.x, a0.y, a0.z, a0.w, a1.x, a1.y, a1.z, a1.w};
            float bb[4] = {b0.x, b0.y, b0.z, b0.w};
            #pragma unroll
            for (int i = 0; i < 8; i++)
                #pragma unroll
                for (int j = 0; j < 4; j++)
                    acc[i][j] = fmaf(a[i], bb[j], acc[i][j]);
        }
        __syncthreads();
    }

    // part[s][m][n]
    float* pbase = part + ((size_t)blockIdx.y * B_) * N;
    #pragma unroll
    for (int i = 0; i < 8; i++) {
        int m = ty * 8 + i;
        float4 v = make_float4(acc[i][0], acc[i][1], acc[i][2], acc[i][3]);
        *reinterpret_cast<float4*>(&pbase[(size_t)m * N + n0 + tx * 4]) = v;
    }
}

// ---------------------------------------------------------------------------
// Epilogue: Y[m][n] = act( sum_s part[s][m][n] + bias[n] )
// ---------------------------------------------------------------------------
template <int RELU>
__global__ __launch_bounds__(256) void reduce_bias_act(
    const float* __restrict__ part, const float* __restrict__ bias,
    float* __restrict__ Y, int N, int S)
{
    int idx4 = blockIdx.x * 256 + threadIdx.x;          // float4 index
    int total4 = (B_ * N) >> 2;
    if (idx4 >= total4) return;
    int n4 = (idx4 << 2) % N;

    float4 s = *reinterpret_cast<const float4*>(&part[(size_t)idx4 << 2]);
    for (int j = 1; j < S; j++) {
        const float4 p = *reinterpret_cast<const float4*>(
            &part[((size_t)j * B_ * N) + ((size_t)idx4 << 2)]);
        s.x += p.x; s.y += p.y; s.z += p.z; s.w += p.w;
    }
    const float4 bv = *reinterpret_cast<const float4*>(&bias[n4]);
    s.x += bv.x; s.y += bv.y; s.z += bv.z; s.w += bv.w;
    if (RELU) {
        s.x = fmaxf(s.x, 0.f); s.y = fmaxf(s.y, 0.f);
        s.z = fmaxf(s.z, 0.f); s.w = fmaxf(s.w, 0.f);
    }
    *reinterpret_cast<float4*>(&Y[(size_t)idx4 << 2]) = s;
}

// ---------------------------------------------------------------------------
// Final layer: [128,512] @ [2,512]^T + b5 -> [128,2]
// ---------------------------------------------------------------------------
__global__ __launch_bounds__(256) void final_layer(
    const float* __restrict__ X, const float* __restrict__ W,
    const float* __restrict__ bias, float* __restrict__ out)
{
    const int t = threadIdx.x;
    const int m = t >> 1;
    const int c = t & 1;
    const float4* xr = reinterpret_cast<const float4*>(X + (size_t)m * H2_);
    const float4* wr = reinterpret_cast<const float4*>(W + (size_t)c * H2_);
    float acc = 0.f;
    #pragma unroll 8
    for (int k = 0; k < H2_ / 4; k++) {
        float4 x = xr[k], w = wr[k];
        acc = fmaf(x.x, w.x, acc); acc = fmaf(x.y, w.y, acc);
        acc = fmaf(x.z, w.z, acc); acc = fmaf(x.w, w.w, acc);
    }
    out[m * 2 + c] = acc + bias[c];
}

// ---------------------------------------------------------------------------
extern "C" void kernel_launch(void* const* d_in, const int* in_sizes, int n_in,
                              void* d_out, int out_size)
{
    const float* stance = (const float*)d_in[0];
    const float* body   = (const float*)d_in[2];
    const float* W1 = (const float*)d_in[4];  const float* b1 = (const float*)d_in[5];
    const float* W2 = (const float*)d_in[6];  const float* b2 = (const float*)d_in[7];
    const float* W3 = (const float*)d_in[8];  const float* b3 = (const float*)d_in[9];
    const float* W4 = (const float*)d_in[10]; const float* b4 = (const float*)d_in[11];
    const float* W5 = (const float*)d_in[12]; const float* b5 = (const float*)d_in[13];

    float *sims, *xx, *h1, *h2, *h3, *h4, *part;
    cudaGetSymbolAddress((void**)&sims, g_sims);
    cudaGetSymbolAddress((void**)&xx,   g_xx);
    cudaGetSymbolAddress((void**)&h1,   g_h1);
    cudaGetSymbolAddress((void**)&h2,   g_h2);
    cudaGetSymbolAddress((void**)&h3,   g_h3);
    cudaGetSymbolAddress((void**)&h4,   g_h4);
    cudaGetSymbolAddress((void**)&part, g_part);

    sims_dots<<<dim3(8, B_), 256>>>(stance, body, sims);
    topk_gather<<<B_, 256>>>(stance, body, sims, xx);

    // L1: [128,2304] x [1024,2304]^T, splitK=9 (chunk 256) -> 16x9 = 144 blocks
    gemm_splitk<<<dim3(H1_ / 64, 9), 256>>>(xx, W1, part, H1_, XXDIM, 256);
    reduce_bias_act<1><<<(B_ * H1_ / 4 + 255) / 256, 256>>>(part, b1, h1, H1_, 9);

    // L2: K=1024, splitK=8 (chunk 128) -> 16x8 = 128 blocks
    gemm_splitk<<<dim3(H1_ / 64, 8), 256>>>(h1, W2, part, H1_, H1_, 128);
    reduce_bias_act<1><<<(B_ * H1_ / 4 + 255) / 256, 256>>>(part, b2, h2, H1_, 8);

    gemm_splitk<<<dim3(H1_ / 64, 8), 256>>>(h2, W3, part, H1_, H1_, 128);
    reduce_bias_act<1><<<(B_ * H1_ / 4 + 255) / 256, 256>>>(part, b3, h3, H1_, 8);

    // L4: N=512, splitK=16 (chunk 64) -> 8x16 = 128 blocks
    gemm_splitk<<<dim3(H2_ / 64, 16), 256>>>(h3, W4, part, H2_, H1_, 64);
    reduce_bias_act<1><<<(B_ * H2_ / 4 + 255) / 256, 256>>>(part, b4, h4, H2_, 16);

    final_layer<<<1, 256>>>(h4, W5, b5, (float*)d_out);
}